// round 1
// baseline (speedup 1.0000x reference)
#include <cuda_runtime.h>
#include <math.h>

// ---------------- problem constants ----------------
#define BB   2
#define CC   128
#define HH   32
#define PP   32768            // 32*32*32 tokens per batch
#define MT   65536            // BB*PP total tokens
#define NHH  8
#define HDD  16
#define NWIN 1024             // BB * 512 windows
#define MLPD 512
#define OUTC 256

// ---------------- scratch (device globals; no allocation allowed) ----------
__device__ float d_h[(size_t)MT * CC];     // residual stream, token-major [b,p,c]
__device__ float d_w[(size_t)MT * CC];     // LN output (window-ordered or token-ordered)
__device__ float d_a[(size_t)MT * MLPD];   // qkv (384) / mlp hidden (512)
__device__ float d_o[(size_t)MT * CC];     // attn out / depthwise out

// ---------------- NCDHW -> token-major transpose ---------------------------
__global__ void transpose_in(const float* __restrict__ x, float* __restrict__ h) {
    __shared__ float tile[32][33];
    int b  = blockIdx.z;
    int p0 = blockIdx.x * 32;
    int c0 = blockIdx.y * 32;
    int tx = threadIdx.x, ty = threadIdx.y;   // (32,8)
#pragma unroll
    for (int i = 0; i < 32; i += 8)
        tile[ty + i][tx] = x[((size_t)b * CC + c0 + ty + i) * PP + p0 + tx];
    __syncthreads();
#pragma unroll
    for (int i = 0; i < 32; i += 8)
        h[((size_t)b * PP + p0 + ty + i) * CC + c0 + tx] = tile[tx][ty + i];
}

// ---------------- LayerNorm (optionally fused shift-roll + window part) ----
// mode 0: out[r] = LN(h[r])                  (token order, for LN2)
// mode 1: out[r] = LN(h[map(r)])             (window order w/ shift, for LN1)
__global__ void ln_kernel(const float* __restrict__ hin,
                          const float* __restrict__ gg, const float* __restrict__ bb,
                          float* __restrict__ out, int mode, int shift) {
    int r = blockIdx.x;
    int tid = threadIdx.x;            // 0..127 = channel
    int src = r;
    if (mode) {
        int nn = r & 63, win = r >> 6;
        int b = win >> 9, widx = win & 511;
        int wh = widx >> 6, ww = (widx >> 3) & 7, wt = widx & 7;
        int ih = nn >> 4,  iw = (nn >> 2) & 3,   it = nn & 3;
        int gh = (wh * 4 + ih + shift) & 31;
        int gw = (ww * 4 + iw + shift) & 31;
        int gt = (wt * 4 + it + shift) & 31;
        src = b * PP + (gh * 32 + gw) * 32 + gt;
    }
    float v = hin[(size_t)src * CC + tid];
    float s = v, sq = v * v;
#pragma unroll
    for (int o = 16; o; o >>= 1) {
        s  += __shfl_xor_sync(~0u, s,  o);
        sq += __shfl_xor_sync(~0u, sq, o);
    }
    __shared__ float ss[4], sqs[4];
    if ((tid & 31) == 0) { ss[tid >> 5] = s; sqs[tid >> 5] = sq; }
    __syncthreads();
    s  = ss[0] + ss[1] + ss[2] + ss[3];
    sq = sqs[0] + sqs[1] + sqs[2] + sqs[3];
    float mean = s * (1.f / CC);
    float var  = sq * (1.f / CC) - mean * mean;
    out[(size_t)r * CC + tid] = (v - mean) * rsqrtf(var + 1e-5f) * gg[tid] + bb[tid];
}

// ---------------- generic SGEMM: out = A[M,K] * W[N,K]^T + bias, fused epi --
// EPI 0: plain store              out[m*N+n] = v
// EPI 1: exact GELU               out[m*N+n] = gelu(v)
// EPI 2: windowed residual add    h[g(m)*C+n] += v   (reverse partition+roll)
// EPI 3: direct residual add      out[m*N+n] += v
// EPI 4: BN+ReLU, NCDHW store     out[(b*256+n)*P + p] = relu(bn(v))
template <int EPI>
__global__ void gemm_nt(const float* __restrict__ A, const float* __restrict__ W,
                        const float* __restrict__ bias, float* __restrict__ out,
                        int Nn, int K, int shift,
                        const float* __restrict__ p1, const float* __restrict__ p2) {
    __shared__ float As[16][64];
    __shared__ float Bs[16][64];
    int tid = threadIdx.x;                 // 256 threads
    int m0 = blockIdx.y * 64, n0 = blockIdx.x * 64;
    int lrow = tid >> 2, lk4 = (tid & 3) * 4;
    const float* Ap = A + (size_t)(m0 + lrow) * K + lk4;
    const float* Wp = W + (size_t)(n0 + lrow) * K + lk4;
    int ty = tid >> 4, tx = tid & 15;
    float acc[4][4] = {};
    for (int kt = 0; kt < K; kt += 16) {
        float4 a4 = *(const float4*)(Ap + kt);
        float4 b4 = *(const float4*)(Wp + kt);
        As[lk4 + 0][lrow] = a4.x; As[lk4 + 1][lrow] = a4.y;
        As[lk4 + 2][lrow] = a4.z; As[lk4 + 3][lrow] = a4.w;
        Bs[lk4 + 0][lrow] = b4.x; Bs[lk4 + 1][lrow] = b4.y;
        Bs[lk4 + 2][lrow] = b4.z; Bs[lk4 + 3][lrow] = b4.w;
        __syncthreads();
#pragma unroll
        for (int k = 0; k < 16; k++) {
            float a[4], b[4];
#pragma unroll
            for (int i = 0; i < 4; i++) a[i] = As[k][ty * 4 + i];
#pragma unroll
            for (int j = 0; j < 4; j++) b[j] = Bs[k][tx * 4 + j];
#pragma unroll
            for (int i = 0; i < 4; i++)
#pragma unroll
                for (int j = 0; j < 4; j++)
                    acc[i][j] += a[i] * b[j];
        }
        __syncthreads();
    }
#pragma unroll
    for (int i = 0; i < 4; i++) {
        int m = m0 + ty * 4 + i;
#pragma unroll
        for (int j = 0; j < 4; j++) {
            int n = n0 + tx * 4 + j;
            float v = acc[i][j] + bias[n];
            if (EPI == 0) {
                out[(size_t)m * Nn + n] = v;
            } else if (EPI == 1) {
                out[(size_t)m * Nn + n] = 0.5f * v * (1.f + erff(v * 0.70710678118f));
            } else if (EPI == 2) {
                int nn = m & 63, win = m >> 6;
                int b = win >> 9, widx = win & 511;
                int wh = widx >> 6, ww = (widx >> 3) & 7, wt = widx & 7;
                int ih = nn >> 4,  iw = (nn >> 2) & 3,   it = nn & 3;
                int gh = (wh * 4 + ih + shift) & 31;
                int gw = (ww * 4 + iw + shift) & 31;
                int gt = (wt * 4 + it + shift) & 31;
                size_t g = (size_t)b * PP + (gh * 32 + gw) * 32 + gt;
                out[g * CC + n] += v;
            } else if (EPI == 3) {
                out[(size_t)m * Nn + n] += v;
            } else if (EPI == 4) {
                int b = m >> 15, p = m & (PP - 1);
                float r = v * rsqrtf(1.0f + 1e-5f) * p1[n] + p2[n];
                out[((size_t)(b * OUTC + n)) * PP + p] = r > 0.f ? r : 0.f;
            }
        }
    }
}

// ---------------- attention: one block per (window, head) ------------------
__global__ void attn_kernel(const float* __restrict__ qkv,
                            const float* __restrict__ rpb,   // already offset: [343,8]
                            float* __restrict__ o, int shift) {
    int win = blockIdx.x;      // 0..1023
    int hh  = blockIdx.y;      // 0..7
    int n   = threadIdx.x;     // 0..63  (query token)
    __shared__ float Ks[64][16], Vs[64][16];
    __shared__ float scs[64][65];
    __shared__ int   rid[64];

    size_t base = (size_t)(win * 64 + n) * 384;
    float q[16];
#pragma unroll
    for (int d = 0; d < 16; d++) q[d] = qkv[base + hh * 16 + d] * 0.25f;
#pragma unroll
    for (int d = 0; d < 16; d++) {
        Ks[n][d] = qkv[base + 128 + hh * 16 + d];
        Vs[n][d] = qkv[base + 256 + hh * 16 + d];
    }
    int ih = n >> 4, iw = (n >> 2) & 3, it = n & 3;
    if (shift) {
        int widx = win & 511;
        int wh = widx >> 6, ww = (widx >> 3) & 7, wt = widx & 7;
        int gh = wh * 4 + ih, gw = ww * 4 + iw, gt = wt * 4 + it;
        int rh = gh < 28 ? 0 : (gh < 30 ? 1 : 2);
        int rw = gw < 28 ? 0 : (gw < 30 ? 1 : 2);
        int rt = gt < 28 ? 0 : (gt < 30 ? 1 : 2);
        rid[n] = rh * 9 + rw * 3 + rt;
    }
    __syncthreads();

    float mx = -1e30f;
    for (int m = 0; m < 64; m++) {
        float s = 0.f;
#pragma unroll
        for (int d = 0; d < 16; d++) s += q[d] * Ks[m][d];
        int mh = m >> 4, mw = (m >> 2) & 3, mt = m & 3;
        int idx = (ih - mh + 3) * 49 + (iw - mw + 3) * 7 + (it - mt + 3);
        s += rpb[idx * 8 + hh];
        if (shift && rid[n] != rid[m]) s -= 100.f;
        scs[n][m] = s;
        mx = fmaxf(mx, s);
    }
    float sum = 0.f;
    for (int m = 0; m < 64; m++) {
        float e = __expf(scs[n][m] - mx);
        scs[n][m] = e;
        sum += e;
    }
    float inv = 1.f / sum;
    float ov[16] = {};
    for (int m = 0; m < 64; m++) {
        float p = scs[n][m];
#pragma unroll
        for (int d = 0; d < 16; d++) ov[d] += p * Vs[m][d];
    }
    size_t ob = (size_t)(win * 64 + n) * CC + hh * 16;
#pragma unroll
    for (int d = 0; d < 16; d++) o[ob + d] = ov[d] * inv;
}

// ---------------- depthwise 3x3x3 conv (SAME, zero pad) --------------------
__global__ void dw_kernel(const float* __restrict__ h, const float* __restrict__ w,
                          float* __restrict__ out) {
    int m = blockIdx.x;               // token 0..65535
    int c = threadIdx.x;              // channel 0..127
    int b = m >> 15, p = m & (PP - 1);
    int ph = p >> 10, pw = (p >> 5) & 31, pt = p & 31;
    float acc = 0.f;
#pragma unroll
    for (int dz = -1; dz <= 1; dz++) {
        int zh = ph + dz;
        if (zh < 0 || zh > 31) continue;
#pragma unroll
        for (int dy = -1; dy <= 1; dy++) {
            int yw = pw + dy;
            if (yw < 0 || yw > 31) continue;
#pragma unroll
            for (int dx = -1; dx <= 1; dx++) {
                int xt = pt + dx;
                if (xt < 0 || xt > 31) continue;
                acc += w[c * 27 + (dz + 1) * 9 + (dy + 1) * 3 + (dx + 1)]
                     * h[((size_t)b * PP + (zh * 32 + yw) * 32 + xt) * CC + c];
            }
        }
    }
    out[(size_t)m * CC + c] = acc;
}

// ---------------- launcher -------------------------------------------------
extern "C" void kernel_launch(void* const* d_in, const int* in_sizes, int n_in,
                              void* d_out, int out_size) {
    const float* x      = (const float*)d_in[0];
    const float* ln1_g  = (const float*)d_in[1];
    const float* ln1_b  = (const float*)d_in[2];
    const float* qkv_w  = (const float*)d_in[3];
    const float* qkv_b  = (const float*)d_in[4];
    const float* proj_w = (const float*)d_in[5];
    const float* proj_b = (const float*)d_in[6];
    const float* rpb    = (const float*)d_in[7];
    const float* ln2_g  = (const float*)d_in[8];
    const float* ln2_b  = (const float*)d_in[9];
    const float* fc1_w  = (const float*)d_in[10];
    const float* fc1_b  = (const float*)d_in[11];
    const float* fc2_w  = (const float*)d_in[12];
    const float* fc2_b  = (const float*)d_in[13];
    const float* dw_w   = (const float*)d_in[14];
    const float* pw_w   = (const float*)d_in[15];
    const float* pw_b   = (const float*)d_in[16];
    const float* bn_g   = (const float*)d_in[17];
    const float* bn_b   = (const float*)d_in[18];
    float* out = (float*)d_out;

    float *h, *wb, *ab, *ob;
    cudaGetSymbolAddress((void**)&h,  d_h);
    cudaGetSymbolAddress((void**)&wb, d_w);
    cudaGetSymbolAddress((void**)&ab, d_a);
    cudaGetSymbolAddress((void**)&ob, d_o);

    transpose_in<<<dim3(PP / 32, CC / 32, BB), dim3(32, 8)>>>(x, h);

    for (int i = 0; i < 4; i++) {
        int shift = (i & 1) ? 2 : 0;
        // LN1 + shift-roll + window partition
        ln_kernel<<<MT, CC>>>(h, ln1_g + i * CC, ln1_b + i * CC, wb, 1, shift);
        // QKV: [65536,128] x [384,128]^T
        gemm_nt<0><<<dim3(384 / 64, MT / 64), 256>>>(
            wb, qkv_w + (size_t)i * 384 * CC, qkv_b + i * 384, ab, 384, CC, 0, nullptr, nullptr);
        // attention per (window, head)
        attn_kernel<<<dim3(NWIN, NHH), 64>>>(ab, rpb + (size_t)i * 343 * NHH, ob, shift);
        // proj + reverse partition/roll + residual add into h
        gemm_nt<2><<<dim3(CC / 64, MT / 64), 256>>>(
            ob, proj_w + (size_t)i * CC * CC, proj_b + i * CC, h, CC, CC, shift, nullptr, nullptr);
        // LN2 (token order)
        ln_kernel<<<MT, CC>>>(h, ln2_g + i * CC, ln2_b + i * CC, wb, 0, 0);
        // fc1 + exact GELU
        gemm_nt<1><<<dim3(MLPD / 64, MT / 64), 256>>>(
            wb, fc1_w + (size_t)i * MLPD * CC, fc1_b + i * MLPD, ab, MLPD, CC, 0, nullptr, nullptr);
        // fc2 + residual add into h
        gemm_nt<3><<<dim3(CC / 64, MT / 64), 256>>>(
            ab, fc2_w + (size_t)i * CC * MLPD, fc2_b + i * CC, h, CC, MLPD, 0, nullptr, nullptr);
    }

    // conv head: depthwise -> pointwise + BN + ReLU (NCDHW store)
    dw_kernel<<<MT, CC>>>(h, dw_w, ob);
    gemm_nt<4><<<dim3(OUTC / 64, MT / 64), 256>>>(
        ob, pw_w, pw_b, out, OUTC, CC, 0, bn_g, bn_b);
}

// round 17
// speedup vs baseline: 1.8684x; 1.8684x over previous
#include <cuda_runtime.h>
#include <cuda_bf16.h>
#include <math.h>
#include <stdint.h>

// ---------------- problem constants ----------------
#define BB   2
#define CC   128
#define PP   32768            // 32*32*32 tokens per batch
#define MT   65536            // BB*PP total tokens
#define NHH  8
#define NWIN 1024             // BB * 512 windows
#define MLPD 512
#define OUTC 256

// ---------------- scratch (device globals) ---------------------------------
__device__ float d_h[(size_t)MT * CC];     // residual stream, token-major
__device__ float d_w[(size_t)MT * CC];     // LN output
__device__ float d_a[(size_t)MT * MLPD];   // qkv (384) / mlp hidden (512)
__device__ float d_o[(size_t)MT * CC];     // attn out / depthwise out

// ---------------- bf16 helpers ---------------------------------------------
__device__ __forceinline__ uint32_t pack_bf2(float a, float b) {
    __nv_bfloat162 t;
    t.x = __float2bfloat16_rn(a);
    t.y = __float2bfloat16_rn(b);
    return *reinterpret_cast<uint32_t*>(&t);
}

__device__ __forceinline__ void mma16816(float* d, const uint32_t* a, const uint32_t* b) {
    asm volatile(
        "mma.sync.aligned.m16n8k16.row.col.f32.bf16.bf16.f32 "
        "{%0,%1,%2,%3}, {%4,%5,%6,%7}, {%8,%9}, {%0,%1,%2,%3};"
        : "+f"(d[0]), "+f"(d[1]), "+f"(d[2]), "+f"(d[3])
        : "r"(a[0]), "r"(a[1]), "r"(a[2]), "r"(a[3]), "r"(b[0]), "r"(b[1]));
}

// ---------------- SMEM layout for MMA GEMM ---------------------------------
// K-chunk = 32 bf16 cols. Row = 16 data words + 4 pad = 20 words (80 B):
// stride 20 ≡ 4 (mod 32) -> fragment LDS (addr word = 20*row + tg) is
// conflict-free across a warp (bank = 4*g + tg + const, all unique).
// Regions per stage: Ahi(10240) Alo(10240) Bhi(10240) Blo(10240) = 40960 B.
// Two stages = 81920 B dynamic SMEM.
#define ROWW   20
#define REG_SZ 10240
#define STG_SZ 40960
#define GT_SMEM (2 * STG_SZ)

// ---------------- tensor-core GEMM: out = A[M,K] * W[N,K]^T + bias ---------
// bf16x3 split: acc += Ahi*Bhi + Ahi*Blo + Alo*Bhi  (rel err ~1e-5)
// EPI 0 plain | 1 exact GELU | 2 windowed residual scatter-add
// EPI 3 residual add | 4 BN+ReLU NCDHW store
template <int EPI>
__global__ void __launch_bounds__(256, 1)
gemm_mma(const float* __restrict__ A, const float* __restrict__ W,
         const float* __restrict__ bias, float* __restrict__ out,
         int Nn, int K, int shift,
         const float* __restrict__ p1, const float* __restrict__ p2) {
    extern __shared__ char smx[];
    int tid = threadIdx.x;
    int wid = tid >> 5, lane = tid & 31;
    int m0 = blockIdx.y * 128, n0 = blockIdx.x * 128;
    int wm = wid & 3, wn = wid >> 2;         // 4 (M) x 2 (N) warps
    int g = lane >> 2, tg = lane & 3;

    float acc[2][8][4];
#pragma unroll
    for (int i = 0; i < 2; i++)
#pragma unroll
        for (int j = 0; j < 8; j++)
#pragma unroll
            for (int k = 0; k < 4; k++) acc[i][j][k] = 0.f;

    const float* Abase = A + (size_t)m0 * K;
    const float* Wbase = W + (size_t)n0 * K;

    float4 av[4], bv[4];
    int nch = K >> 5;

    // ---- gmem chunk load into registers (A and B tiles are 128x32 fp32) ---
    auto ldg_chunk = [&](int c) {
#pragma unroll
        for (int j = 0; j < 4; j++) {
            int idx = tid + j * 256;         // float4 index 0..1023
            int row = idx >> 3, c4 = idx & 7;
            av[j] = *(const float4*)(Abase + (size_t)row * K + c * 32 + c4 * 4);
            bv[j] = *(const float4*)(Wbase + (size_t)row * K + c * 32 + c4 * 4);
        }
    };
    // ---- convert + store registers into stage s ---------------------------
    auto sts_chunk = [&](int s) {
        char* st = smx + s * STG_SZ;
#pragma unroll
        for (int j = 0; j < 4; j++) {
            int idx = tid + j * 256;
            int row = idx >> 3, c4 = idx & 7;
            uint32_t off = (uint32_t)row * 80 + (uint32_t)c4 * 8;
            {
                float4 v = av[j];
                float hx = __bfloat162float(__float2bfloat16_rn(v.x));
                float hy = __bfloat162float(__float2bfloat16_rn(v.y));
                float hz = __bfloat162float(__float2bfloat16_rn(v.z));
                float hw = __bfloat162float(__float2bfloat16_rn(v.w));
                uint2 hi, lo;
                hi.x = pack_bf2(hx, hy); hi.y = pack_bf2(hz, hw);
                lo.x = pack_bf2(v.x - hx, v.y - hy);
                lo.y = pack_bf2(v.z - hz, v.w - hw);
                *(uint2*)(st + off) = hi;
                *(uint2*)(st + REG_SZ + off) = lo;
            }
            {
                float4 v = bv[j];
                float hx = __bfloat162float(__float2bfloat16_rn(v.x));
                float hy = __bfloat162float(__float2bfloat16_rn(v.y));
                float hz = __bfloat162float(__float2bfloat16_rn(v.z));
                float hw = __bfloat162float(__float2bfloat16_rn(v.w));
                uint2 hi, lo;
                hi.x = pack_bf2(hx, hy); hi.y = pack_bf2(hz, hw);
                lo.x = pack_bf2(v.x - hx, v.y - hy);
                lo.y = pack_bf2(v.z - hz, v.w - hw);
                *(uint2*)(st + 2 * REG_SZ + off) = hi;
                *(uint2*)(st + 3 * REG_SZ + off) = lo;
            }
        }
    };
    // ---- compute one K-chunk (two k16 steps) from stage s -----------------
    auto compute = [&](int s) {
        const uint32_t* Ah = (const uint32_t*)(smx + s * STG_SZ);
        const uint32_t* Al = (const uint32_t*)(smx + s * STG_SZ + REG_SZ);
        const uint32_t* Bh = (const uint32_t*)(smx + s * STG_SZ + 2 * REG_SZ);
        const uint32_t* Bl = (const uint32_t*)(smx + s * STG_SZ + 3 * REG_SZ);
#pragma unroll
        for (int ks = 0; ks < 2; ks++) {
            int ko = ks * 8;
            uint32_t ahi[2][4], alo[2][4];
#pragma unroll
            for (int im = 0; im < 2; im++) {
                int rb = wm * 32 + im * 16;
                ahi[im][0] = Ah[(rb + g) * ROWW + tg + ko];
                ahi[im][1] = Ah[(rb + g + 8) * ROWW + tg + ko];
                ahi[im][2] = Ah[(rb + g) * ROWW + tg + 4 + ko];
                ahi[im][3] = Ah[(rb + g + 8) * ROWW + tg + 4 + ko];
                alo[im][0] = Al[(rb + g) * ROWW + tg + ko];
                alo[im][1] = Al[(rb + g + 8) * ROWW + tg + ko];
                alo[im][2] = Al[(rb + g) * ROWW + tg + 4 + ko];
                alo[im][3] = Al[(rb + g + 8) * ROWW + tg + 4 + ko];
            }
            uint32_t bhi[8][2], blo[8][2];
#pragma unroll
            for (int jn = 0; jn < 8; jn++) {
                int nb = wn * 64 + jn * 8;
                bhi[jn][0] = Bh[(nb + g) * ROWW + tg + ko];
                bhi[jn][1] = Bh[(nb + g) * ROWW + tg + 4 + ko];
                blo[jn][0] = Bl[(nb + g) * ROWW + tg + ko];
                blo[jn][1] = Bl[(nb + g) * ROWW + tg + 4 + ko];
            }
#pragma unroll
            for (int im = 0; im < 2; im++)
#pragma unroll
                for (int jn = 0; jn < 8; jn++) {
                    mma16816(acc[im][jn], ahi[im], bhi[jn]);
                    mma16816(acc[im][jn], ahi[im], blo[jn]);
                    mma16816(acc[im][jn], alo[im], bhi[jn]);
                }
        }
    };

    // ---- pipelined mainloop ----------------------------------------------
    ldg_chunk(0);
    sts_chunk(0);
    __syncthreads();
    for (int c = 0; c < nch; c++) {
        if (c + 1 < nch) ldg_chunk(c + 1);
        compute(c & 1);
        __syncthreads();
        if (c + 1 < nch) {
            sts_chunk((c + 1) & 1);
            __syncthreads();
        }
    }

    // ---- epilogue ---------------------------------------------------------
#pragma unroll
    for (int im = 0; im < 2; im++) {
#pragma unroll
        for (int half = 0; half < 2; half++) {
            int m = m0 + wm * 32 + im * 16 + g + half * 8;
            size_t gbase = 0;
            if (EPI == 2) {
                int nn = m & 63, win = m >> 6;
                int b = win >> 9, widx = win & 511;
                int wh = widx >> 6, ww = (widx >> 3) & 7, wt = widx & 7;
                int ih = nn >> 4,  iw = (nn >> 2) & 3,   it = nn & 3;
                int gh = (wh * 4 + ih + shift) & 31;
                int gw = (ww * 4 + iw + shift) & 31;
                int gt = (wt * 4 + it + shift) & 31;
                gbase = ((size_t)b * PP + (gh * 32 + gw) * 32 + gt) * CC;
            }
            int bq = m >> 15, p = m & (PP - 1);   // for EPI 4
#pragma unroll
            for (int jn = 0; jn < 8; jn++) {
                int n = n0 + wn * 64 + jn * 8 + 2 * tg;
                float v0 = acc[im][jn][half * 2 + 0] + bias[n];
                float v1 = acc[im][jn][half * 2 + 1] + bias[n + 1];
                if (EPI == 0) {
                    *(float2*)(out + (size_t)m * Nn + n) = make_float2(v0, v1);
                } else if (EPI == 1) {
                    v0 = 0.5f * v0 * (1.f + erff(v0 * 0.70710678118f));
                    v1 = 0.5f * v1 * (1.f + erff(v1 * 0.70710678118f));
                    *(float2*)(out + (size_t)m * Nn + n) = make_float2(v0, v1);
                } else if (EPI == 2) {
                    out[gbase + n]     += v0;
                    out[gbase + n + 1] += v1;
                } else if (EPI == 3) {
                    out[(size_t)m * Nn + n]     += v0;
                    out[(size_t)m * Nn + n + 1] += v1;
                } else if (EPI == 4) {
                    float r0 = v0 * rsqrtf(1.0f + 1e-5f) * p1[n] + p2[n];
                    float r1 = v1 * rsqrtf(1.0f + 1e-5f) * p1[n + 1] + p2[n + 1];
                    out[((size_t)(bq * OUTC + n)) * PP + p]     = r0 > 0.f ? r0 : 0.f;
                    out[((size_t)(bq * OUTC + n + 1)) * PP + p] = r1 > 0.f ? r1 : 0.f;
                }
            }
        }
    }
}

// ---------------- NCDHW -> token-major transpose ---------------------------
__global__ void transpose_in(const float* __restrict__ x, float* __restrict__ h) {
    __shared__ float tile[32][33];
    int b = blockIdx.z, p0 = blockIdx.x * 32, c0 = blockIdx.y * 32;
    int tx = threadIdx.x, ty = threadIdx.y;
#pragma unroll
    for (int i = 0; i < 32; i += 8)
        tile[ty + i][tx] = x[((size_t)b * CC + c0 + ty + i) * PP + p0 + tx];
    __syncthreads();
#pragma unroll
    for (int i = 0; i < 32; i += 8)
        h[((size_t)b * PP + p0 + ty + i) * CC + c0 + tx] = tile[tx][ty + i];
}

// ---------------- LayerNorm (optionally fused shift-roll + partition) ------
__global__ void ln_kernel(const float* __restrict__ hin,
                          const float* __restrict__ gg, const float* __restrict__ bb,
                          float* __restrict__ out, int mode, int shift) {
    int r = blockIdx.x, tid = threadIdx.x;
    int src = r;
    if (mode) {
        int nn = r & 63, win = r >> 6;
        int b = win >> 9, widx = win & 511;
        int wh = widx >> 6, ww = (widx >> 3) & 7, wt = widx & 7;
        int ih = nn >> 4,  iw = (nn >> 2) & 3,   it = nn & 3;
        int gh = (wh * 4 + ih + shift) & 31;
        int gw = (ww * 4 + iw + shift) & 31;
        int gt = (wt * 4 + it + shift) & 31;
        src = b * PP + (gh * 32 + gw) * 32 + gt;
    }
    float v = hin[(size_t)src * CC + tid];
    float s = v, sq = v * v;
#pragma unroll
    for (int o = 16; o; o >>= 1) {
        s  += __shfl_xor_sync(~0u, s,  o);
        sq += __shfl_xor_sync(~0u, sq, o);
    }
    __shared__ float ss[4], sqs[4];
    if ((tid & 31) == 0) { ss[tid >> 5] = s; sqs[tid >> 5] = sq; }
    __syncthreads();
    s  = ss[0] + ss[1] + ss[2] + ss[3];
    sq = sqs[0] + sqs[1] + sqs[2] + sqs[3];
    float mean = s * (1.f / CC);
    float var  = sq * (1.f / CC) - mean * mean;
    out[(size_t)r * CC + tid] = (v - mean) * rsqrtf(var + 1e-5f) * gg[tid] + bb[tid];
}

// ---------------- attention: one block per window, 512 threads -------------
__global__ void __launch_bounds__(512, 2)
attn2(const float* __restrict__ qkv, const float* __restrict__ rpb,
      float* __restrict__ o, int shift) {
    extern __shared__ float s[];                // Ks[64*128], Vs[64*128], rid[64]
    float* Ks = s;
    float* Vs = s + 8192;
    int*   rid = (int*)(s + 16384);
    int win = blockIdx.x;
    int tx = threadIdx.x, hh = threadIdx.y;
    int tid = hh * 64 + tx;
    const float* base = qkv + (size_t)win * 64 * 384;

    for (int idx = tid; idx < 64 * 32; idx += 512) {
        int m = idx >> 5, c4 = idx & 31;
        *(float4*)(Ks + m * 128 + c4 * 4) = *(const float4*)(base + m * 384 + 128 + c4 * 4);
        *(float4*)(Vs + m * 128 + c4 * 4) = *(const float4*)(base + m * 384 + 256 + c4 * 4);
    }
    float q[16];
    {
        const float* qp = base + tx * 384 + hh * 16;
#pragma unroll
        for (int d4 = 0; d4 < 4; d4++) {
            float4 t = *(const float4*)(qp + d4 * 4);
            q[d4 * 4 + 0] = t.x * 0.25f; q[d4 * 4 + 1] = t.y * 0.25f;
            q[d4 * 4 + 2] = t.z * 0.25f; q[d4 * 4 + 3] = t.w * 0.25f;
        }
    }
    int ih = tx >> 4, iw = (tx >> 2) & 3, it = tx & 3;
    if (shift && hh == 0) {
        int widx = win & 511;
        int wh = widx >> 6, ww = (widx >> 3) & 7, wt = widx & 7;
        int gh = wh * 4 + ih, gw = ww * 4 + iw, gt = wt * 4 + it;
        int rh = gh < 28 ? 0 : (gh < 30 ? 1 : 2);
        int rw = gw < 28 ? 0 : (gw < 30 ? 1 : 2);
        int rt = gt < 28 ? 0 : (gt < 30 ? 1 : 2);
        rid[tx] = rh * 9 + rw * 3 + rt;
    }
    __syncthreads();

    const float* Kh = Ks + hh * 16;
    const float* Vh = Vs + hh * 16;
    int myrid = shift ? rid[tx] : 0;

    float mx = -1e30f;
    for (int m = 0; m < 64; m++) {
        const float* kr = Kh + m * 128;
        float sd = 0.f;
#pragma unroll
        for (int d = 0; d < 16; d++) sd += q[d] * kr[d];
        int mh = m >> 4, mw = (m >> 2) & 3, mt = m & 3;
        sd += rpb[((ih - mh + 3) * 49 + (iw - mw + 3) * 7 + (it - mt + 3)) * 8 + hh];
        if (shift && myrid != rid[m]) sd -= 100.f;
        mx = fmaxf(mx, sd);
    }
    float sum = 0.f, ov[16] = {};
    for (int m = 0; m < 64; m++) {
        const float* kr = Kh + m * 128;
        float sd = 0.f;
#pragma unroll
        for (int d = 0; d < 16; d++) sd += q[d] * kr[d];
        int mh = m >> 4, mw = (m >> 2) & 3, mt = m & 3;
        sd += rpb[((ih - mh + 3) * 49 + (iw - mw + 3) * 7 + (it - mt + 3)) * 8 + hh];
        if (shift && myrid != rid[m]) sd -= 100.f;
        float e = __expf(sd - mx);
        sum += e;
        const float* vr = Vh + m * 128;
#pragma unroll
        for (int d = 0; d < 16; d++) ov[d] += e * vr[d];
    }
    float inv = 1.f / sum;
    float* op = o + ((size_t)win * 64 + tx) * CC + hh * 16;
#pragma unroll
    for (int d4 = 0; d4 < 4; d4++) {
        float4 t;
        t.x = ov[d4 * 4 + 0] * inv; t.y = ov[d4 * 4 + 1] * inv;
        t.z = ov[d4 * 4 + 2] * inv; t.w = ov[d4 * 4 + 3] * inv;
        *(float4*)(op + d4 * 4) = t;
    }
}

// ---------------- depthwise 3x3x3 conv -------------------------------------
__global__ void dw_kernel(const float* __restrict__ h, const float* __restrict__ w,
                          float* __restrict__ out) {
    int m = blockIdx.x, c = threadIdx.x;
    int b = m >> 15, p = m & (PP - 1);
    int ph = p >> 10, pw = (p >> 5) & 31, pt = p & 31;
    float acc = 0.f;
#pragma unroll
    for (int dz = -1; dz <= 1; dz++) {
        int zh = ph + dz;
        if (zh < 0 || zh > 31) continue;
#pragma unroll
        for (int dy = -1; dy <= 1; dy++) {
            int yw = pw + dy;
            if (yw < 0 || yw > 31) continue;
#pragma unroll
            for (int dx = -1; dx <= 1; dx++) {
                int xt = pt + dx;
                if (xt < 0 || xt > 31) continue;
                acc += w[c * 27 + (dz + 1) * 9 + (dy + 1) * 3 + (dx + 1)]
                     * h[((size_t)b * PP + (zh * 32 + yw) * 32 + xt) * CC + c];
            }
        }
    }
    out[(size_t)m * CC + c] = acc;
}

// ---------------- launcher -------------------------------------------------
extern "C" void kernel_launch(void* const* d_in, const int* in_sizes, int n_in,
                              void* d_out, int out_size) {
    const float* x      = (const float*)d_in[0];
    const float* ln1_g  = (const float*)d_in[1];
    const float* ln1_b  = (const float*)d_in[2];
    const float* qkv_w  = (const float*)d_in[3];
    const float* qkv_b  = (const float*)d_in[4];
    const float* proj_w = (const float*)d_in[5];
    const float* proj_b = (const float*)d_in[6];
    const float* rpb    = (const float*)d_in[7];
    const float* ln2_g  = (const float*)d_in[8];
    const float* ln2_b  = (const float*)d_in[9];
    const float* fc1_w  = (const float*)d_in[10];
    const float* fc1_b  = (const float*)d_in[11];
    const float* fc2_w  = (const float*)d_in[12];
    const float* fc2_b  = (const float*)d_in[13];
    const float* dw_w   = (const float*)d_in[14];
    const float* pw_w   = (const float*)d_in[15];
    const float* pw_b   = (const float*)d_in[16];
    const float* bn_g   = (const float*)d_in[17];
    const float* bn_b   = (const float*)d_in[18];
    float* out = (float*)d_out;

    float *h, *wb, *ab, *ob;
    cudaGetSymbolAddress((void**)&h,  d_h);
    cudaGetSymbolAddress((void**)&wb, d_w);
    cudaGetSymbolAddress((void**)&ab, d_a);
    cudaGetSymbolAddress((void**)&ob, d_o);

    cudaFuncSetAttribute(gemm_mma<0>, cudaFuncAttributeMaxDynamicSharedMemorySize, GT_SMEM);
    cudaFuncSetAttribute(gemm_mma<1>, cudaFuncAttributeMaxDynamicSharedMemorySize, GT_SMEM);
    cudaFuncSetAttribute(gemm_mma<2>, cudaFuncAttributeMaxDynamicSharedMemorySize, GT_SMEM);
    cudaFuncSetAttribute(gemm_mma<3>, cudaFuncAttributeMaxDynamicSharedMemorySize, GT_SMEM);
    cudaFuncSetAttribute(gemm_mma<4>, cudaFuncAttributeMaxDynamicSharedMemorySize, GT_SMEM);
    const int ATTN_SMEM = 64 * 128 * 4 * 2 + 64 * 4;
    cudaFuncSetAttribute(attn2, cudaFuncAttributeMaxDynamicSharedMemorySize, ATTN_SMEM);

    transpose_in<<<dim3(PP / 32, CC / 32, BB), dim3(32, 8)>>>(x, h);

    for (int i = 0; i < 4; i++) {
        int shift = (i & 1) ? 2 : 0;
        ln_kernel<<<MT, CC>>>(h, ln1_g + i * CC, ln1_b + i * CC, wb, 1, shift);
        gemm_mma<0><<<dim3(3, MT / 128), 256, GT_SMEM>>>(
            wb, qkv_w + (size_t)i * 384 * CC, qkv_b + i * 384, ab, 384, CC, 0, nullptr, nullptr);
        attn2<<<NWIN, dim3(64, 8), ATTN_SMEM>>>(ab, rpb + (size_t)i * 343 * NHH, ob, shift);
        gemm_mma<2><<<dim3(1, MT / 128), 256, GT_SMEM>>>(
            ob, proj_w + (size_t)i * CC * CC, proj_b + i * CC, h, CC, CC, shift, nullptr, nullptr);
        ln_kernel<<<MT, CC>>>(h, ln2_g + i * CC, ln2_b + i * CC, wb, 0, 0);
        gemm_mma<1><<<dim3(4, MT / 128), 256, GT_SMEM>>>(
            wb, fc1_w + (size_t)i * MLPD * CC, fc1_b + i * MLPD, ab, MLPD, CC, 0, nullptr, nullptr);
        gemm_mma<3><<<dim3(1, MT / 128), 256, GT_SMEM>>>(
            ab, fc2_w + (size_t)i * CC * MLPD, fc2_b + i * CC, h, CC, MLPD, 0, nullptr, nullptr);
    }

    dw_kernel<<<MT, CC>>>(h, dw_w, ob);
    gemm_mma<4><<<dim3(2, MT / 128), 256, GT_SMEM>>>(
        ob, pw_w, pw_b, out, OUTC, CC, 0, bn_g, bn_b);
}